// round 15
// baseline (speedup 1.0000x reference)
#include <cuda_runtime.h>
#include <cuda_bf16.h>
#include <cstdint>

// Shapes (fixed): pointcloud (4,16384,3) f32; keys (4096,3) f32; values (4096,64) f32
// Output f32: feats (65536,64) | ids (65536) | pointcloud (196608) = 4456448 elems

#define BN       65536
#define M_KEYS   4096
#define D_FEAT   64
#define PC_ELEMS 196608

#define FEATS_OFF 0
#define IDS_OFF   4194304
#define PC_OFF    4259840

#define NSLICE   8
#define SLICE_M  (M_KEYS / NSLICE)      // 512 keys per slice
#define SLICE_P  (SLICE_M / 2)          // 256 key-pairs per slice

#define TPB      128                     // threads per block (argmin) — R14-proven
#define PPT      4                       // points per thread — R14-proven
#define PTS_BLK  (TPB * PPT)             // 512 points per block -> 1024 blocks

typedef unsigned long long ull;

// ---- packed f32x2 helpers (each half = exact scalar fp32 op) ----
#define FMA2(out, a, b, c) \
    asm("fma.rn.f32x2 %0, %1, %2, %3;" : "=l"(out) : "l"(a), "l"(b), "l"(c))
#define MUL2(out, a, b) \
    asm("mul.rn.f32x2 %0, %1, %2;" : "=l"(out) : "l"(a), "l"(b))
#define ADD2(out, a, b) \
    asm("add.rn.f32x2 %0, %1, %2;" : "=l"(out) : "l"(a), "l"(b))
#define PACK2(out, lo, hi) \
    asm("mov.b64 %0, {%1, %2};" : "=l"(out) : "f"(lo), "f"(hi))
#define UNPACK2(lo, hi, in) \
    asm("mov.b64 {%0, %1}, %2;" : "=f"(lo), "=f"(hi) : "l"(in))

// Key-pair struct: a = (kx0,kx1,ky0,ky1), b = (kz0,kz1,ksq0,ksq1)
struct KeyPair { float4 a; float4 b; };

// Device scratch (no allocs allowed in kernel_launch).
// Per-slice packed partial results: (ord(d2) << 32) | key_idx. Plain stores,
// no atomics, no init needed (every slot is written every call).
__device__ ull g_part[NSLICE * BN];

// ---------------------------------------------------------------------------
// Kernel 1: sliced argmin. Inner loop EXACTLY as R14 (proven rel_err 0.0).
// Changes vs R14: (a) key slice staged from raw keys in-block (kills the
// prep kernel; ksq uses the identical fmaf chain), (b) result written as a
// plain coalesced STG to g_part[slice][point] (kills init kernel + atomics).
// Per-half arithmetic (bit-exact form):
//   cross = fmaf(pz,kz, fmaf(py,ky, px*kx));  d2 = fmaf(-2,cross,psq) + ksq
// In-loop: dm = fminf(d0,d1); strict (dm < best) updates {best, iwin}.
// Post-loop: recompute winning pair (identical chain -> bit-identical),
// resolve half via (d1 < d0); strict '<' ascending == jnp.argmin first-min.
// ---------------------------------------------------------------------------
__global__ void __launch_bounds__(TPB) argmin_slice_kernel(
    const float* __restrict__ pc,
    const float* __restrict__ keys)
{
    __shared__ KeyPair sk[SLICE_P];   // 8KB

    const int base = blockIdx.y * SLICE_M;

    // Stage + pack this block's key slice from raw keys (2 pairs/thread).
#pragma unroll
    for (int i = threadIdx.x; i < SLICE_P; i += TPB) {
        int j0 = base + 2 * i;
        float kx0 = __ldg(&keys[3*j0+0]), ky0 = __ldg(&keys[3*j0+1]), kz0 = __ldg(&keys[3*j0+2]);
        float kx1 = __ldg(&keys[3*j0+3]), ky1 = __ldg(&keys[3*j0+4]), kz1 = __ldg(&keys[3*j0+5]);
        float q0 = fmaf(kz0, kz0, fmaf(ky0, ky0, kx0 * kx0));
        float q1 = fmaf(kz1, kz1, fmaf(ky1, ky1, kx1 * kx1));
        KeyPair kp;
        kp.a = make_float4(kx0, kx1, ky0, ky1);
        kp.b = make_float4(kz0, kz1, q0, q1);
        sk[i] = kp;
    }
    __syncthreads();

    const int p0 = blockIdx.x * PTS_BLK + threadIdx.x;

    ull px2[PPT], py2[PPT], pz2[PPT], psq2[PPT], n22;
    PACK2(n22, -2.0f, -2.0f);
#pragma unroll
    for (int k = 0; k < PPT; ++k) {
        int p = p0 + k * TPB;
        float px = pc[3 * p + 0];
        float py = pc[3 * p + 1];
        float pz = pc[3 * p + 2];
        float psq = fmaf(pz, pz, fmaf(py, py, px * px));
        PACK2(px2[k], px, px);
        PACK2(py2[k], py, py);
        PACK2(pz2[k], pz, pz);
        PACK2(psq2[k], psq, psq);
    }

    float best[PPT];
    int   iwin[PPT];
#pragma unroll
    for (int k = 0; k < PPT; ++k) {
        best[k] = __int_as_float(0x7f800000);   // +inf
        iwin[k] = 0;
    }

#pragma unroll 2
    for (int i = 0; i < SLICE_P; ++i) {
        float4 a = sk[i].a;   // kx0,kx1,ky0,ky1
        float4 b = sk[i].b;   // kz0,kz1,q0,q1
        ull kx01, ky01, kz01, q01;
        PACK2(kx01, a.x, a.y);
        PACK2(ky01, a.z, a.w);
        PACK2(kz01, b.x, b.y);
        PACK2(q01,  b.z, b.w);

#pragma unroll
        for (int k = 0; k < PPT; ++k) {
            ull c, t, d;
            MUL2(c, px2[k], kx01);
            FMA2(c, py2[k], ky01, c);
            FMA2(c, pz2[k], kz01, c);
            FMA2(t, n22, c, psq2[k]);
            ADD2(d, t, q01);
            float d0, d1;
            UNPACK2(d0, d1, d);
            float dm = fminf(d0, d1);
            if (dm < best[k]) { best[k] = dm; iwin[k] = i; }
        }
    }

    // Post-loop half-bit recovery + plain coalesced partial store.
#pragma unroll
    for (int k = 0; k < PPT; ++k) {
        int i = iwin[k];
        float4 a = sk[i].a;
        float4 b = sk[i].b;
        ull kx01, ky01, kz01, q01, c, t, d;
        PACK2(kx01, a.x, a.y);
        PACK2(ky01, a.z, a.w);
        PACK2(kz01, b.x, b.y);
        PACK2(q01,  b.z, b.w);
        MUL2(c, px2[k], kx01);
        FMA2(c, py2[k], ky01, c);
        FMA2(c, pz2[k], kz01, c);
        FMA2(t, n22, c, psq2[k]);
        ADD2(d, t, q01);
        float d0, d1;
        UNPACK2(d0, d1, d);
        int bidx = base + 2 * i + ((d1 < d0) ? 1 : 0);

        unsigned u = __float_as_uint(best[k]);
        u = (u & 0x80000000u) ? ~u : (u | 0x80000000u);
        ull packed = ((ull)u << 32) | (unsigned)bidx;
        g_part[blockIdx.y * BN + p0 + k * TPB] = packed;
    }
}

// ---------------------------------------------------------------------------
// Kernel 2: reduce 8 slice partials per point (shfl u64 min, lexicographic
// == first-min), emit ids, gather values row, copy pointcloud.
// 8 threads/point: lane q reads g_part[q][point]; 3x shfl_xor(width 8) min;
// each lane then copies 2 float4 of the values row (MLP 2).
// ---------------------------------------------------------------------------
__global__ void __launch_bounds__(256) gather_kernel(
    const float* __restrict__ pc,
    const float* __restrict__ values,
    float* __restrict__ out)
{
    int t = blockIdx.x * blockDim.x + threadIdx.x;

    // Fold pointcloud copy into the first 49152 threads (float4 stride).
    if (t < PC_ELEMS / 4) {
        reinterpret_cast<float4*>(out + PC_OFF)[t] =
            reinterpret_cast<const float4*>(pc)[t];
    }

    int point = t >> 3;
    int q     = t & 7;
    if (point >= BN) return;

    // Lane q holds slice q's partial; reduce across the 8-lane group.
    ull packed = g_part[q * BN + point];
    packed = min(packed, __shfl_xor_sync(0xFFFFFFFFu, packed, 1, 8));
    packed = min(packed, __shfl_xor_sync(0xFFFFFFFFu, packed, 2, 8));
    packed = min(packed, __shfl_xor_sync(0xFFFFFFFFu, packed, 4, 8));
    int id = (int)(packed & 0xFFFFFFFFu);

    if (q == 0) out[IDS_OFF + point] = (float)id;

    const float4* src = reinterpret_cast<const float4*>(values + (size_t)id * D_FEAT);
    float4* dst = reinterpret_cast<float4*>(out + FEATS_OFF + (size_t)point * D_FEAT);
    dst[q] = src[q];
    dst[q + 8] = src[q + 8];
}

// ---------------------------------------------------------------------------
extern "C" void kernel_launch(void* const* d_in, const int* in_sizes, int n_in,
                              void* d_out, int out_size) {
    const float* pc     = (const float*)d_in[0];
    const float* keys   = (const float*)d_in[1];
    const float* values = (const float*)d_in[2];
    float* out = (float*)d_out;

    dim3 grid(BN / PTS_BLK, NSLICE);
    argmin_slice_kernel<<<grid, TPB>>>(pc, keys);

    gather_kernel<<<(BN * 8 + 255) / 256, 256>>>(pc, values, out);
}

// round 16
// speedup vs baseline: 1.0837x; 1.0837x over previous
#include <cuda_runtime.h>
#include <cuda_bf16.h>
#include <cstdint>

// Shapes (fixed): pointcloud (4,16384,3) f32; keys (4096,3) f32; values (4096,64) f32
// Output f32: feats (65536,64) | ids (65536) | pointcloud (196608) = 4456448 elems

#define BN       65536
#define M_KEYS   4096
#define D_FEAT   64
#define PC_ELEMS 196608

#define FEATS_OFF 0
#define IDS_OFF   4194304
#define PC_OFF    4259840

#define NSLICE   16
#define SLICE_M  (M_KEYS / NSLICE)      // 256 keys per slice
#define SLICE_P  (SLICE_M / 2)          // 128 key-pairs per slice

#define TPB      128                     // threads per block (argmin) — R14-proven
#define PPT      4                       // points per thread — R14-proven
#define PTS_BLK  (TPB * PPT)             // 512 points per block -> 2048 blocks

typedef unsigned long long ull;

// ---- packed f32x2 helpers (each half = exact scalar fp32 op) ----
#define FMA2(out, a, b, c) \
    asm("fma.rn.f32x2 %0, %1, %2, %3;" : "=l"(out) : "l"(a), "l"(b), "l"(c))
#define MUL2(out, a, b) \
    asm("mul.rn.f32x2 %0, %1, %2;" : "=l"(out) : "l"(a), "l"(b))
#define ADD2(out, a, b) \
    asm("add.rn.f32x2 %0, %1, %2;" : "=l"(out) : "l"(a), "l"(b))
#define PACK2(out, lo, hi) \
    asm("mov.b64 %0, {%1, %2};" : "=l"(out) : "f"(lo), "f"(hi))
#define UNPACK2(lo, hi, in) \
    asm("mov.b64 {%0, %1}, %2;" : "=f"(lo), "=f"(hi) : "l"(in))

// Key-pair struct: a = (kx0,kx1,ky0,ky1), b = (kz0,kz1,ksq0,ksq1)
struct KeyPair { float4 a; float4 b; };

// Device scratch (no allocs allowed in kernel_launch).
__device__ KeyPair g_kp[M_KEYS / 2];
__device__ ull g_best[BN];   // (ordered_d2_bits << 32) | key_idx

// ---------------------------------------------------------------------------
// Kernel 0: fused prep (key pairs + ||k||^2) and best-init.  (R14-proven)
// ---------------------------------------------------------------------------
__global__ void __launch_bounds__(256) prep_kernel(const float* __restrict__ keys) {
    int t = blockIdx.x * blockDim.x + threadIdx.x;
    if (t < BN) g_best[t] = 0xFFFFFFFFFFFFFFFFULL;
    if (t < M_KEYS / 2) {
        int j0 = 2 * t;
        float kx0 = keys[3*j0+0], ky0 = keys[3*j0+1], kz0 = keys[3*j0+2];
        float kx1 = keys[3*j0+3], ky1 = keys[3*j0+4], kz1 = keys[3*j0+5];
        float q0 = fmaf(kz0, kz0, fmaf(ky0, ky0, kx0 * kx0));
        float q1 = fmaf(kz1, kz1, fmaf(ky1, ky1, kx1 * kx1));
        KeyPair kp;
        kp.a = make_float4(kx0, kx1, ky0, ky1);
        kp.b = make_float4(kz0, kz1, q0, q1);
        g_kp[t] = kp;
    }
}

// ---------------------------------------------------------------------------
// Kernel 1: sliced argmin. Arithmetic/semantics identical to R14 (proven
// rel_err 0.0); changes: NSLICE 8->16 (doubles warp pool 4096->8192 for
// latency hiding; per-warp state unchanged) and unroll 4.
// Per-half arithmetic (bit-exact form):
//   cross = fmaf(pz,kz, fmaf(py,ky, px*kx));  d2 = fmaf(-2,cross,psq) + ksq
// In-loop: dm = fminf(d0,d1); strict (dm < best) updates {best, iwin}.
// Post-loop: recompute winning pair (identical chain -> bit-identical),
// resolve half via (d1 < d0); strict '<' ascending == jnp.argmin first-min.
// Cross-slice merge via lexicographic u64 atomicMin on (ordered_bits, idx).
// ---------------------------------------------------------------------------
__global__ void __launch_bounds__(TPB) argmin_slice_kernel(
    const float* __restrict__ pc)
{
    __shared__ KeyPair sk[SLICE_P];   // 4KB

    const int base = blockIdx.y * SLICE_M;

#pragma unroll
    for (int i = threadIdx.x; i < SLICE_P; i += TPB)
        sk[i] = g_kp[blockIdx.y * SLICE_P + i];
    __syncthreads();

    const int p0 = blockIdx.x * PTS_BLK + threadIdx.x;

    ull px2[PPT], py2[PPT], pz2[PPT], psq2[PPT], n22;
    PACK2(n22, -2.0f, -2.0f);
#pragma unroll
    for (int k = 0; k < PPT; ++k) {
        int p = p0 + k * TPB;
        float px = pc[3 * p + 0];
        float py = pc[3 * p + 1];
        float pz = pc[3 * p + 2];
        float psq = fmaf(pz, pz, fmaf(py, py, px * px));
        PACK2(px2[k], px, px);
        PACK2(py2[k], py, py);
        PACK2(pz2[k], pz, pz);
        PACK2(psq2[k], psq, psq);
    }

    float best[PPT];
    int   iwin[PPT];
#pragma unroll
    for (int k = 0; k < PPT; ++k) {
        best[k] = __int_as_float(0x7f800000);   // +inf
        iwin[k] = 0;
    }

#pragma unroll 4
    for (int i = 0; i < SLICE_P; ++i) {
        float4 a = sk[i].a;   // kx0,kx1,ky0,ky1
        float4 b = sk[i].b;   // kz0,kz1,q0,q1
        ull kx01, ky01, kz01, q01;
        PACK2(kx01, a.x, a.y);
        PACK2(ky01, a.z, a.w);
        PACK2(kz01, b.x, b.y);
        PACK2(q01,  b.z, b.w);

#pragma unroll
        for (int k = 0; k < PPT; ++k) {
            ull c, t, d;
            MUL2(c, px2[k], kx01);
            FMA2(c, py2[k], ky01, c);
            FMA2(c, pz2[k], kz01, c);
            FMA2(t, n22, c, psq2[k]);
            ADD2(d, t, q01);
            float d0, d1;
            UNPACK2(d0, d1, d);
            float dm = fminf(d0, d1);
            if (dm < best[k]) { best[k] = dm; iwin[k] = i; }
        }
    }

    // Post-loop half-bit recovery + packed merge.
#pragma unroll
    for (int k = 0; k < PPT; ++k) {
        int i = iwin[k];
        float4 a = sk[i].a;
        float4 b = sk[i].b;
        ull kx01, ky01, kz01, q01, c, t, d;
        PACK2(kx01, a.x, a.y);
        PACK2(ky01, a.z, a.w);
        PACK2(kz01, b.x, b.y);
        PACK2(q01,  b.z, b.w);
        MUL2(c, px2[k], kx01);
        FMA2(c, py2[k], ky01, c);
        FMA2(c, pz2[k], kz01, c);
        FMA2(t, n22, c, psq2[k]);
        ADD2(d, t, q01);
        float d0, d1;
        UNPACK2(d0, d1, d);
        int bidx = base + 2 * i + ((d1 < d0) ? 1 : 0);

        unsigned u = __float_as_uint(best[k]);
        u = (u & 0x80000000u) ? ~u : (u | 0x80000000u);
        ull packed = ((ull)u << 32) | (unsigned)bidx;
        atomicMin(&g_best[p0 + k * TPB], packed);
    }
}

// ---------------------------------------------------------------------------
// Kernel 2: gather values rows into feats + emit ids + copy pointcloud.
// 16 threads/point, float4 lanes.  (R14-proven)
// ---------------------------------------------------------------------------
__global__ void __launch_bounds__(256) gather_kernel(
    const float* __restrict__ pc,
    const float* __restrict__ values,
    float* __restrict__ out)
{
    int t = blockIdx.x * blockDim.x + threadIdx.x;

    if (t < PC_ELEMS / 4) {
        reinterpret_cast<float4*>(out + PC_OFF)[t] =
            reinterpret_cast<const float4*>(pc)[t];
    }

    int point = t >> 4;
    int q     = t & 15;
    if (point >= BN) return;

    int id = (int)(g_best[point] & 0xFFFFFFFFu);   // broadcast load
    if (q == 0) out[IDS_OFF + point] = (float)id;

    const float4* src = reinterpret_cast<const float4*>(values + (size_t)id * D_FEAT);
    float4* dst = reinterpret_cast<float4*>(out + FEATS_OFF + (size_t)point * D_FEAT);
    dst[q] = src[q];
}

// ---------------------------------------------------------------------------
extern "C" void kernel_launch(void* const* d_in, const int* in_sizes, int n_in,
                              void* d_out, int out_size) {
    const float* pc     = (const float*)d_in[0];
    const float* keys   = (const float*)d_in[1];
    const float* values = (const float*)d_in[2];
    float* out = (float*)d_out;

    prep_kernel<<<(BN + 255) / 256, 256>>>(keys);

    dim3 grid(BN / PTS_BLK, NSLICE);
    argmin_slice_kernel<<<grid, TPB>>>(pc);

    gather_kernel<<<(BN * 16 + 255) / 256, 256>>>(pc, values, out);
}

// round 17
// speedup vs baseline: 1.1245x; 1.0377x over previous
#include <cuda_runtime.h>
#include <cuda_bf16.h>
#include <cstdint>

// Shapes (fixed): pointcloud (4,16384,3) f32; keys (4096,3) f32; values (4096,64) f32
// Output f32: feats (65536,64) | ids (65536) | pointcloud (196608) = 4456448 elems

#define BN       65536
#define M_KEYS   4096
#define D_FEAT   64
#define PC_ELEMS 196608

#define FEATS_OFF 0
#define IDS_OFF   4194304
#define PC_OFF    4259840

#define NSLICE   32
#define SLICE_M  (M_KEYS / NSLICE)      // 128 keys per slice
#define SLICE_P  (SLICE_M / 2)          // 64 key-pairs per slice

#define TPB      128                     // threads per block (argmin) — proven
#define PPT      4                       // points per thread — proven
#define PTS_BLK  (TPB * PPT)             // 512 points per block -> 4096 blocks

typedef unsigned long long ull;

// ---- packed f32x2 helpers (each half = exact scalar fp32 op) ----
#define FMA2(out, a, b, c) \
    asm("fma.rn.f32x2 %0, %1, %2, %3;" : "=l"(out) : "l"(a), "l"(b), "l"(c))
#define MUL2(out, a, b) \
    asm("mul.rn.f32x2 %0, %1, %2;" : "=l"(out) : "l"(a), "l"(b))
#define ADD2(out, a, b) \
    asm("add.rn.f32x2 %0, %1, %2;" : "=l"(out) : "l"(a), "l"(b))
#define PACK2(out, lo, hi) \
    asm("mov.b64 %0, {%1, %2};" : "=l"(out) : "f"(lo), "f"(hi))
#define UNPACK2(lo, hi, in) \
    asm("mov.b64 {%0, %1}, %2;" : "=f"(lo), "=f"(hi) : "l"(in))

// Key-pair struct: a = (kx0,kx1,ky0,ky1), b = (kz0,kz1,ksq0,ksq1)
struct KeyPair { float4 a; float4 b; };

// Device scratch (no allocs allowed in kernel_launch).
__device__ KeyPair g_kp[M_KEYS / 2];
__device__ ull g_best[BN];   // (ordered_d2_bits << 32) | key_idx

// ---------------------------------------------------------------------------
// Kernel 0: fused prep (key pairs + ||k||^2) and best-init.  (proven)
// ---------------------------------------------------------------------------
__global__ void __launch_bounds__(256) prep_kernel(const float* __restrict__ keys) {
    int t = blockIdx.x * blockDim.x + threadIdx.x;
    if (t < BN) g_best[t] = 0xFFFFFFFFFFFFFFFFULL;
    if (t < M_KEYS / 2) {
        int j0 = 2 * t;
        float kx0 = keys[3*j0+0], ky0 = keys[3*j0+1], kz0 = keys[3*j0+2];
        float kx1 = keys[3*j0+3], ky1 = keys[3*j0+4], kz1 = keys[3*j0+5];
        float q0 = fmaf(kz0, kz0, fmaf(ky0, ky0, kx0 * kx0));
        float q1 = fmaf(kz1, kz1, fmaf(ky1, ky1, kx1 * kx1));
        KeyPair kp;
        kp.a = make_float4(kx0, kx1, ky0, ky1);
        kp.b = make_float4(kz0, kz1, q0, q1);
        g_kp[t] = kp;
    }
}

// ---------------------------------------------------------------------------
// Kernel 1: sliced argmin. Arithmetic/semantics identical to R14/R16 (proven
// rel_err 0.0); single change vs R16: NSLICE 16->32 (warp pool 8192->16384).
// Per-half arithmetic (bit-exact form):
//   cross = fmaf(pz,kz, fmaf(py,ky, px*kx));  d2 = fmaf(-2,cross,psq) + ksq
// In-loop: dm = fminf(d0,d1); strict (dm < best) updates {best, iwin}.
// Post-loop: recompute winning pair (identical chain -> bit-identical),
// resolve half via (d1 < d0); strict '<' ascending == jnp.argmin first-min.
// Cross-slice merge via lexicographic u64 atomicMin on (ordered_bits, idx).
// ---------------------------------------------------------------------------
__global__ void __launch_bounds__(TPB) argmin_slice_kernel(
    const float* __restrict__ pc)
{
    __shared__ KeyPair sk[SLICE_P];   // 2KB

    const int base = blockIdx.y * SLICE_M;

#pragma unroll
    for (int i = threadIdx.x; i < SLICE_P; i += TPB)
        sk[i] = g_kp[blockIdx.y * SLICE_P + i];
    __syncthreads();

    const int p0 = blockIdx.x * PTS_BLK + threadIdx.x;

    ull px2[PPT], py2[PPT], pz2[PPT], psq2[PPT], n22;
    PACK2(n22, -2.0f, -2.0f);
#pragma unroll
    for (int k = 0; k < PPT; ++k) {
        int p = p0 + k * TPB;
        float px = pc[3 * p + 0];
        float py = pc[3 * p + 1];
        float pz = pc[3 * p + 2];
        float psq = fmaf(pz, pz, fmaf(py, py, px * px));
        PACK2(px2[k], px, px);
        PACK2(py2[k], py, py);
        PACK2(pz2[k], pz, pz);
        PACK2(psq2[k], psq, psq);
    }

    float best[PPT];
    int   iwin[PPT];
#pragma unroll
    for (int k = 0; k < PPT; ++k) {
        best[k] = __int_as_float(0x7f800000);   // +inf
        iwin[k] = 0;
    }

#pragma unroll 4
    for (int i = 0; i < SLICE_P; ++i) {
        float4 a = sk[i].a;   // kx0,kx1,ky0,ky1
        float4 b = sk[i].b;   // kz0,kz1,q0,q1
        ull kx01, ky01, kz01, q01;
        PACK2(kx01, a.x, a.y);
        PACK2(ky01, a.z, a.w);
        PACK2(kz01, b.x, b.y);
        PACK2(q01,  b.z, b.w);

#pragma unroll
        for (int k = 0; k < PPT; ++k) {
            ull c, t, d;
            MUL2(c, px2[k], kx01);
            FMA2(c, py2[k], ky01, c);
            FMA2(c, pz2[k], kz01, c);
            FMA2(t, n22, c, psq2[k]);
            ADD2(d, t, q01);
            float d0, d1;
            UNPACK2(d0, d1, d);
            float dm = fminf(d0, d1);
            if (dm < best[k]) { best[k] = dm; iwin[k] = i; }
        }
    }

    // Post-loop half-bit recovery + packed merge.
#pragma unroll
    for (int k = 0; k < PPT; ++k) {
        int i = iwin[k];
        float4 a = sk[i].a;
        float4 b = sk[i].b;
        ull kx01, ky01, kz01, q01, c, t, d;
        PACK2(kx01, a.x, a.y);
        PACK2(ky01, a.z, a.w);
        PACK2(kz01, b.x, b.y);
        PACK2(q01,  b.z, b.w);
        MUL2(c, px2[k], kx01);
        FMA2(c, py2[k], ky01, c);
        FMA2(c, pz2[k], kz01, c);
        FMA2(t, n22, c, psq2[k]);
        ADD2(d, t, q01);
        float d0, d1;
        UNPACK2(d0, d1, d);
        int bidx = base + 2 * i + ((d1 < d0) ? 1 : 0);

        unsigned u = __float_as_uint(best[k]);
        u = (u & 0x80000000u) ? ~u : (u | 0x80000000u);
        ull packed = ((ull)u << 32) | (unsigned)bidx;
        atomicMin(&g_best[p0 + k * TPB], packed);
    }
}

// ---------------------------------------------------------------------------
// Kernel 2: gather values rows into feats + emit ids + copy pointcloud.
// 16 threads/point, float4 lanes.  (proven)
// ---------------------------------------------------------------------------
__global__ void __launch_bounds__(256) gather_kernel(
    const float* __restrict__ pc,
    const float* __restrict__ values,
    float* __restrict__ out)
{
    int t = blockIdx.x * blockDim.x + threadIdx.x;

    if (t < PC_ELEMS / 4) {
        reinterpret_cast<float4*>(out + PC_OFF)[t] =
            reinterpret_cast<const float4*>(pc)[t];
    }

    int point = t >> 4;
    int q     = t & 15;
    if (point >= BN) return;

    int id = (int)(g_best[point] & 0xFFFFFFFFu);   // broadcast load
    if (q == 0) out[IDS_OFF + point] = (float)id;

    const float4* src = reinterpret_cast<const float4*>(values + (size_t)id * D_FEAT);
    float4* dst = reinterpret_cast<float4*>(out + FEATS_OFF + (size_t)point * D_FEAT);
    dst[q] = src[q];
}

// ---------------------------------------------------------------------------
extern "C" void kernel_launch(void* const* d_in, const int* in_sizes, int n_in,
                              void* d_out, int out_size) {
    const float* pc     = (const float*)d_in[0];
    const float* keys   = (const float*)d_in[1];
    const float* values = (const float*)d_in[2];
    float* out = (float*)d_out;

    prep_kernel<<<(BN + 255) / 256, 256>>>(keys);

    dim3 grid(BN / PTS_BLK, NSLICE);
    argmin_slice_kernel<<<grid, TPB>>>(pc);

    gather_kernel<<<(BN * 16 + 255) / 256, 256>>>(pc, values, out);
}